// round 13
// baseline (speedup 1.0000x reference)
#include <cuda_runtime.h>
#include <cuda_fp16.h>
#include <math.h>

// Problem constants (from reference)
#define NNODES 50000
#define NEDGES 800000
#define DIN    128
#define DOUT   128
#define NTOT   (2 * NEDGES)
#define NB_SCAN ((NNODES + 255) / 256)   // 196 scan blocks

// Scratch (static device arrays — no allocation allowed)
__device__ float  g_z[(size_t)NNODES * DIN];    // 25.6 MB mixed aggregation buffer
__device__ __half g_xh[(size_t)NNODES * DIN];   // 12.8 MB fp16 copy of x (gather source)
__device__ float  g_alpha[NNODES];
__device__ int    g_cnt[NNODES];                // histogram
__device__ int    g_start[NNODES + 1];          // CSR row starts (exclusive scan)
__device__ int    g_cur[NNODES];                // placement cursors
__device__ int2   g_edge[NTOT];                 // {col | (is_lp<<30), f32_bits(val)}
__device__ int    g_bsum[NB_SCAN];              // per-block partial sums
__device__ int    g_boff[NB_SCAN];              // per-block exclusive offsets

// ---------------------------------------------------------------------------
// Kernel: zero the histogram
// ---------------------------------------------------------------------------
__global__ void zero_cnt_kernel() {
    int i = blockIdx.x * blockDim.x + threadIdx.x;
    if (i < NNODES) g_cnt[i] = 0;
}

// ---------------------------------------------------------------------------
// Kernel: convert x -> fp16 (4 floats per thread: float4 in, uint2 out)
// ---------------------------------------------------------------------------
__global__ void convert_x_kernel(const float* __restrict__ x) {
    int i = blockIdx.x * blockDim.x + threadIdx.x;   // 1.6M quads
    const int total4 = NNODES * DIN / 4;
    if (i >= total4) return;
    float4 v = reinterpret_cast<const float4*>(x)[i];
    __half2 h0 = __floats2half2_rn(v.x, v.y);
    __half2 h1 = __floats2half2_rn(v.z, v.w);
    uint2 p;
    p.x = *reinterpret_cast<unsigned int*>(&h0);
    p.y = *reinterpret_cast<unsigned int*>(&h1);
    reinterpret_cast<uint2*>(g_xh)[i] = p;
}

// ---------------------------------------------------------------------------
// Kernel: per-node gate alpha = sigmoid(x_i . theta + b). One warp per node.
// ---------------------------------------------------------------------------
__global__ void alpha_kernel(const float* __restrict__ x,
                             const float* __restrict__ aw,
                             const float* __restrict__ ab,
                             float* __restrict__ alpha_out) {
    int warp = (blockIdx.x * blockDim.x + threadIdx.x) >> 5;
    int lane = threadIdx.x & 31;
    if (warp >= NNODES) return;
    float4 xv = reinterpret_cast<const float4*>(x + (size_t)warp * DIN)[lane];
    float4 wv = reinterpret_cast<const float4*>(aw)[lane];
    float s = xv.x * wv.x + xv.y * wv.y + xv.z * wv.z + xv.w * wv.w;
    #pragma unroll
    for (int o = 16; o > 0; o >>= 1) s += __shfl_xor_sync(0xffffffffu, s, o);
    if (lane == 0) {
        float a = 1.0f / (1.0f + expf(-(s + ab[0])));
        g_alpha[warp]   = a;
        alpha_out[warp] = a;
    }
}

// ---------------------------------------------------------------------------
// Kernel: histogram of destination rows over the combined lp+hp edge stream
// ---------------------------------------------------------------------------
__global__ void hist_kernel(const int* __restrict__ lpr,
                            const int* __restrict__ hpr) {
    int i = blockIdx.x * blockDim.x + threadIdx.x;
    if (i < NEDGES)      atomicAdd(&g_cnt[lpr[i]], 1);
    else if (i < NTOT)   atomicAdd(&g_cnt[hpr[i - NEDGES]], 1);
}

// ---------------------------------------------------------------------------
// 3-phase full-chip exclusive scan of g_cnt (50000 ints)
// ---------------------------------------------------------------------------
__global__ void scan_a_kernel() {
    int idx = blockIdx.x * 256 + threadIdx.x;
    int c = (idx < NNODES) ? g_cnt[idx] : 0;
    int lane = threadIdx.x & 31, wid = threadIdx.x >> 5;
    #pragma unroll
    for (int o = 16; o > 0; o >>= 1) c += __shfl_xor_sync(0xffffffffu, c, o);
    __shared__ int ws[8];
    if (lane == 0) ws[wid] = c;
    __syncthreads();
    if (threadIdx.x == 0) {
        int s = 0;
        #pragma unroll
        for (int w = 0; w < 8; w++) s += ws[w];
        g_bsum[blockIdx.x] = s;
    }
}

__global__ void scan_b_kernel() {
    int t = threadIdx.x;                 // 256 threads, NB_SCAN=196 live
    int c = (t < NB_SCAN) ? g_bsum[t] : 0;
    int lane = t & 31, wid = t >> 5;
    int v = c;
    #pragma unroll
    for (int o = 1; o < 32; o <<= 1) {
        int n = __shfl_up_sync(0xffffffffu, v, o);
        if (lane >= o) v += n;
    }
    __shared__ int ws[8];
    if (lane == 31) ws[wid] = v;
    __syncthreads();
    if (wid == 0 && lane < 8) {
        int u = ws[lane];
        #pragma unroll
        for (int o = 1; o < 8; o <<= 1) {
            int n = __shfl_up_sync(0x000000ffu, u, o);
            if (lane >= o) u += n;
        }
        ws[lane] = u;
    }
    __syncthreads();
    int incl = v + (wid > 0 ? ws[wid - 1] : 0);
    if (t < NB_SCAN) g_boff[t] = incl - c;   // exclusive
}

__global__ void scan_c_kernel() {
    int b = blockIdx.x, t = threadIdx.x;
    int idx = b * 256 + t;
    int c = (idx < NNODES) ? g_cnt[idx] : 0;
    int lane = t & 31, wid = t >> 5;
    int v = c;
    #pragma unroll
    for (int o = 1; o < 32; o <<= 1) {
        int n = __shfl_up_sync(0xffffffffu, v, o);
        if (lane >= o) v += n;
    }
    __shared__ int ws[8];
    if (lane == 31) ws[wid] = v;
    __syncthreads();
    if (wid == 0 && lane < 8) {
        int u = ws[lane];
        #pragma unroll
        for (int o = 1; o < 8; o <<= 1) {
            int n = __shfl_up_sync(0x000000ffu, u, o);
            if (lane >= o) u += n;
        }
        ws[lane] = u;
    }
    __syncthreads();
    int excl = (v - c) + (wid > 0 ? ws[wid - 1] : 0) + g_boff[b];
    if (idx < NNODES) {
        g_start[idx] = excl;
        g_cur[idx]   = excl;
    }
    if (b == 0 && t == 0) g_start[NNODES] = NTOT;
}

// ---------------------------------------------------------------------------
// Kernel: place edges into CSR slots (packed int2: one 8B store per edge)
// ---------------------------------------------------------------------------
__global__ void place_kernel(const int* __restrict__ lpr, const int* __restrict__ lpc,
                             const float* __restrict__ lpv,
                             const int* __restrict__ hpr, const int* __restrict__ hpc,
                             const float* __restrict__ hpv) {
    int i = blockIdx.x * blockDim.x + threadIdx.x;
    if (i >= NTOT) return;
    int row, col, flag;
    float val;
    if (i < NEDGES) {
        row = lpr[i]; col = lpc[i]; val = lpv[i]; flag = 1;
    } else {
        int e = i - NEDGES;
        row = hpr[e]; col = hpc[e]; val = hpv[e]; flag = 0;
    }
    int pos = atomicAdd(&g_cur[row], 1);
    g_edge[pos] = make_int2(col | (flag << 30), __float_as_int(val));
}

// ---------------------------------------------------------------------------
// Kernel: atomic-free aggregate. One warp per destination row; lane owns 4
// features gathered as fp16 (uint2 = 4 halves), accumulated in fp32.
// 4-deep unroll for MLP.
// ---------------------------------------------------------------------------
__device__ __forceinline__ float edge_w(int c, float v, float a, float ia) {
    return (c & 0x40000000) ? a * v : ia * v;
}

__device__ __forceinline__ void acc_half4(float4& acc, float w, uint2 h) {
    __half2 h0 = *reinterpret_cast<__half2*>(&h.x);
    __half2 h1 = *reinterpret_cast<__half2*>(&h.y);
    float2 f0 = __half22float2(h0);
    float2 f1 = __half22float2(h1);
    acc.x = fmaf(w, f0.x, acc.x); acc.y = fmaf(w, f0.y, acc.y);
    acc.z = fmaf(w, f1.x, acc.z); acc.w = fmaf(w, f1.y, acc.w);
}

__global__ void aggregate_kernel() {
    int warp = (blockIdx.x * blockDim.x + threadIdx.x) >> 5;
    int lane = threadIdx.x & 31;
    if (warp >= NNODES) return;

    int s = g_start[warp];
    int e = g_start[warp + 1];
    float a  = g_alpha[warp];
    float ia = 1.0f - a;

    float4 acc = make_float4(0.f, 0.f, 0.f, 0.f);

    int i = s;
    for (; i + 3 < e; i += 4) {
        int2 e0 = g_edge[i],     e1 = g_edge[i + 1];
        int2 e2 = g_edge[i + 2], e3 = g_edge[i + 3];
        uint2 x0 = reinterpret_cast<const uint2*>(g_xh + (size_t)(e0.x & 0x3FFFFFFF) * DIN)[lane];
        uint2 x1 = reinterpret_cast<const uint2*>(g_xh + (size_t)(e1.x & 0x3FFFFFFF) * DIN)[lane];
        uint2 x2 = reinterpret_cast<const uint2*>(g_xh + (size_t)(e2.x & 0x3FFFFFFF) * DIN)[lane];
        uint2 x3 = reinterpret_cast<const uint2*>(g_xh + (size_t)(e3.x & 0x3FFFFFFF) * DIN)[lane];
        float w0 = edge_w(e0.x, __int_as_float(e0.y), a, ia);
        float w1 = edge_w(e1.x, __int_as_float(e1.y), a, ia);
        float w2 = edge_w(e2.x, __int_as_float(e2.y), a, ia);
        float w3 = edge_w(e3.x, __int_as_float(e3.y), a, ia);
        acc_half4(acc, w0, x0);
        acc_half4(acc, w1, x1);
        acc_half4(acc, w2, x2);
        acc_half4(acc, w3, x3);
    }
    for (; i < e; i++) {
        int2 e0 = g_edge[i];
        uint2 x0 = reinterpret_cast<const uint2*>(g_xh + (size_t)(e0.x & 0x3FFFFFFF) * DIN)[lane];
        float w0 = edge_w(e0.x, __int_as_float(e0.y), a, ia);
        acc_half4(acc, w0, x0);
    }

    reinterpret_cast<float4*>(g_z + (size_t)warp * DIN)[lane] = acc;
}

// ---------------------------------------------------------------------------
// Kernel: out = relu(z_mix @ W^T + b). 128x128x8 SGEMM, 8x8 microtile,
// packed fma.rn.f32x2 (FFMA2) inner loop.
// ---------------------------------------------------------------------------
#define GBM 128
#define GBK 8
#define LDS_PAD 132   // 128 + 4, keeps float4 alignment (132*4 % 16 == 0)

__global__ void __launch_bounds__(256)
gemm_relu_kernel(const float* __restrict__ W,
                 const float* __restrict__ bias,
                 float* __restrict__ out) {
    __shared__ float As[GBK][LDS_PAD];  // As[k][m]
    __shared__ float Bs[GBK][LDS_PAD];  // Bs[k][n] = W[n][k]

    const int tid = threadIdx.x;        // 0..255
    const int tx  = tid & 15;           // n-group: 16 groups of 8 cols
    const int ty  = tid >> 4;           // m-group: 16 groups of 8 rows
    const int m0  = blockIdx.x * GBM;

    const int lrow = tid >> 1;          // 0..127 (staging row)
    const int lkq  = (tid & 1) * 4;     // 0 or 4 (staging k quad)

    unsigned long long acc[8][4];
    #pragma unroll
    for (int i = 0; i < 8; i++)
        #pragma unroll
        for (int j = 0; j < 4; j++) acc[i][j] = 0ull;

    for (int k0 = 0; k0 < DIN; k0 += GBK) {
        {
            int gm = m0 + lrow;
            float4 v = make_float4(0.f, 0.f, 0.f, 0.f);
            if (gm < NNODES)
                v = reinterpret_cast<const float4*>(g_z + (size_t)gm * DIN + k0 + lkq)[0];
            As[lkq + 0][lrow] = v.x; As[lkq + 1][lrow] = v.y;
            As[lkq + 2][lrow] = v.z; As[lkq + 3][lrow] = v.w;
        }
        {
            float4 v = reinterpret_cast<const float4*>(
                W + (size_t)lrow * DIN + k0 + lkq)[0];
            Bs[lkq + 0][lrow] = v.x; Bs[lkq + 1][lrow] = v.y;
            Bs[lkq + 2][lrow] = v.z; Bs[lkq + 3][lrow] = v.w;
        }
        __syncthreads();

        #pragma unroll
        for (int kk = 0; kk < GBK; kk++) {
            float a[8];
            {
                float4 a0 = reinterpret_cast<const float4*>(&As[kk][ty * 8])[0];
                float4 a1 = reinterpret_cast<const float4*>(&As[kk][ty * 8])[1];
                a[0]=a0.x; a[1]=a0.y; a[2]=a0.z; a[3]=a0.w;
                a[4]=a1.x; a[5]=a1.y; a[6]=a1.z; a[7]=a1.w;
            }
            unsigned long long bp[4];
            {
                const ulonglong2* bq = reinterpret_cast<const ulonglong2*>(&Bs[kk][tx * 8]);
                ulonglong2 q0 = bq[0], q1 = bq[1];
                bp[0] = q0.x; bp[1] = q0.y; bp[2] = q1.x; bp[3] = q1.y;
            }
            #pragma unroll
            for (int i = 0; i < 8; i++) {
                unsigned long long ap;
                asm("mov.b64 %0, {%1, %1};" : "=l"(ap) : "f"(a[i]));
                asm("fma.rn.f32x2 %0, %1, %2, %0;" : "+l"(acc[i][0]) : "l"(ap), "l"(bp[0]));
                asm("fma.rn.f32x2 %0, %1, %2, %0;" : "+l"(acc[i][1]) : "l"(ap), "l"(bp[1]));
                asm("fma.rn.f32x2 %0, %1, %2, %0;" : "+l"(acc[i][2]) : "l"(ap), "l"(bp[2]));
                asm("fma.rn.f32x2 %0, %1, %2, %0;" : "+l"(acc[i][3]) : "l"(ap), "l"(bp[3]));
            }
        }
        __syncthreads();
    }

    #pragma unroll
    for (int i = 0; i < 8; i++) {
        int gm = m0 + ty * 8 + i;
        if (gm >= NNODES) continue;
        #pragma unroll
        for (int jp = 0; jp < 4; jp += 2) {
            int gn = tx * 8 + jp * 2;
            float c0, c1, c2, c3;
            asm("mov.b64 {%0, %1}, %2;" : "=f"(c0), "=f"(c1) : "l"(acc[i][jp]));
            asm("mov.b64 {%0, %1}, %2;" : "=f"(c2), "=f"(c3) : "l"(acc[i][jp + 1]));
            float4 v;
            v.x = c0 + bias[gn + 0];
            v.y = c1 + bias[gn + 1];
            v.z = c2 + bias[gn + 2];
            v.w = c3 + bias[gn + 3];
            v.x = v.x > 0.f ? v.x : 0.f;
            v.y = v.y > 0.f ? v.y : 0.f;
            v.z = v.z > 0.f ? v.z : 0.f;
            v.w = v.w > 0.f ? v.w : 0.f;
            reinterpret_cast<float4*>(out + (size_t)gm * DOUT + gn)[0] = v;
        }
    }
}

// ---------------------------------------------------------------------------
// Launch
// Inputs: x, lp_rows, lp_cols, lp_vals, hp_rows, hp_cols, hp_vals,
//         alpha_w, alpha_b, W, b
// Output: [out (N*DOUT floats)] then [alpha (N floats)]
// ---------------------------------------------------------------------------
extern "C" void kernel_launch(void* const* d_in, const int* in_sizes, int n_in,
                              void* d_out, int out_size) {
    const float* x   = (const float*)d_in[0];
    const int*   lpr = (const int*)  d_in[1];
    const int*   lpc = (const int*)  d_in[2];
    const float* lpv = (const float*)d_in[3];
    const int*   hpr = (const int*)  d_in[4];
    const int*   hpc = (const int*)  d_in[5];
    const float* hpv = (const float*)d_in[6];
    const float* aw  = (const float*)d_in[7];
    const float* ab  = (const float*)d_in[8];
    const float* W   = (const float*)d_in[9];
    const float* b   = (const float*)d_in[10];

    float* out       = (float*)d_out;
    float* alpha_out = (float*)d_out + (out_size - NNODES);

    // 1) zero histogram + fp16 convert of x
    zero_cnt_kernel<<<(NNODES + 255) / 256, 256>>>();
    convert_x_kernel<<<(NNODES * DIN / 4 + 255) / 256, 256>>>(x);

    // 2) alpha gate (one warp per node)
    alpha_kernel<<<(NNODES + 7) / 8, 256>>>(x, aw, ab, alpha_out);

    // 3) histogram of destination rows
    hist_kernel<<<(NTOT + 255) / 256, 256>>>(lpr, hpr);

    // 4) 3-phase exclusive scan -> CSR row starts + cursors
    scan_a_kernel<<<NB_SCAN, 256>>>();
    scan_b_kernel<<<1, 256>>>();
    scan_c_kernel<<<NB_SCAN, 256>>>();

    // 5) place edges into CSR slots (packed int2)
    place_kernel<<<(NTOT + 255) / 256, 256>>>(lpr, lpc, lpv, hpr, hpc, hpv);

    // 6) atomic-free gather-aggregate (fp16 gather, fp32 accumulate)
    aggregate_kernel<<<(NNODES + 7) / 8, 256>>>();

    // 7) GEMM + bias + relu (128x128x8, 8x8 microtile, FFMA2)
    gemm_relu_kernel<<<(NNODES + GBM - 1) / GBM, 256>>>(W, b, out);
}

// round 16
// speedup vs baseline: 1.0002x; 1.0002x over previous
#include <cuda_runtime.h>
#include <cuda_fp16.h>
#include <math.h>

// Problem constants (from reference)
#define NNODES 50000
#define NEDGES 800000
#define DIN    128
#define DOUT   128
#define NTOT   (2 * NEDGES)
#define NB_SCAN ((NNODES + 255) / 256)   // 196 scan blocks

// Scratch (static device arrays — no allocation allowed)
__device__ __half g_yh[(size_t)NNODES * DOUT];  // 12.8 MB fp16 y = x @ W^T
__device__ float  g_alpha[NNODES];
__device__ int    g_cnt[NNODES];                // histogram
__device__ int    g_start[NNODES + 1];          // CSR row starts (exclusive scan)
__device__ int    g_rank[NTOT];                 // within-row rank per edge
__device__ int2   g_edge[NTOT];                 // {col | (is_lp<<30), f32_bits(val)}
__device__ int    g_bsum[NB_SCAN];              // per-block partial sums
__device__ int    g_boff[NB_SCAN];              // per-block exclusive offsets

// ---------------------------------------------------------------------------
// Kernel: zero the histogram
// ---------------------------------------------------------------------------
__global__ void zero_cnt_kernel() {
    int i = blockIdx.x * blockDim.x + threadIdx.x;
    if (i < NNODES) g_cnt[i] = 0;
}

// ---------------------------------------------------------------------------
// Kernel: per-node gate alpha = sigmoid(x_i . theta + b). One warp per node.
// ---------------------------------------------------------------------------
__global__ void alpha_kernel(const float* __restrict__ x,
                             const float* __restrict__ aw,
                             const float* __restrict__ ab,
                             float* __restrict__ alpha_out) {
    int warp = (blockIdx.x * blockDim.x + threadIdx.x) >> 5;
    int lane = threadIdx.x & 31;
    if (warp >= NNODES) return;
    float4 xv = reinterpret_cast<const float4*>(x + (size_t)warp * DIN)[lane];
    float4 wv = reinterpret_cast<const float4*>(aw)[lane];
    float s = xv.x * wv.x + xv.y * wv.y + xv.z * wv.z + xv.w * wv.w;
    #pragma unroll
    for (int o = 16; o > 0; o >>= 1) s += __shfl_xor_sync(0xffffffffu, s, o);
    if (lane == 0) {
        float a = 1.0f / (1.0f + expf(-(s + ab[0])));
        g_alpha[warp]   = a;
        alpha_out[warp] = a;
    }
}

// ---------------------------------------------------------------------------
// Kernel: histogram + within-row rank (single atomic pass; rank reused by
// place so place needs no atomics)
// ---------------------------------------------------------------------------
__global__ void hist_rank_kernel(const int* __restrict__ lpr,
                                 const int* __restrict__ hpr) {
    int i = blockIdx.x * blockDim.x + threadIdx.x;
    if (i < NEDGES)      g_rank[i] = atomicAdd(&g_cnt[lpr[i]], 1);
    else if (i < NTOT)   g_rank[i] = atomicAdd(&g_cnt[hpr[i - NEDGES]], 1);
}

// ---------------------------------------------------------------------------
// 3-phase full-chip exclusive scan of g_cnt (50000 ints)
// ---------------------------------------------------------------------------
__global__ void scan_a_kernel() {
    int idx = blockIdx.x * 256 + threadIdx.x;
    int c = (idx < NNODES) ? g_cnt[idx] : 0;
    int lane = threadIdx.x & 31, wid = threadIdx.x >> 5;
    #pragma unroll
    for (int o = 16; o > 0; o >>= 1) c += __shfl_xor_sync(0xffffffffu, c, o);
    __shared__ int ws[8];
    if (lane == 0) ws[wid] = c;
    __syncthreads();
    if (threadIdx.x == 0) {
        int s = 0;
        #pragma unroll
        for (int w = 0; w < 8; w++) s += ws[w];
        g_bsum[blockIdx.x] = s;
    }
}

__global__ void scan_b_kernel() {
    int t = threadIdx.x;                 // 256 threads, NB_SCAN=196 live
    int c = (t < NB_SCAN) ? g_bsum[t] : 0;
    int lane = t & 31, wid = t >> 5;
    int v = c;
    #pragma unroll
    for (int o = 1; o < 32; o <<= 1) {
        int n = __shfl_up_sync(0xffffffffu, v, o);
        if (lane >= o) v += n;
    }
    __shared__ int ws[8];
    if (lane == 31) ws[wid] = v;
    __syncthreads();
    if (wid == 0 && lane < 8) {
        int u = ws[lane];
        #pragma unroll
        for (int o = 1; o < 8; o <<= 1) {
            int n = __shfl_up_sync(0x000000ffu, u, o);
            if (lane >= o) u += n;
        }
        ws[lane] = u;
    }
    __syncthreads();
    int incl = v + (wid > 0 ? ws[wid - 1] : 0);
    if (t < NB_SCAN) g_boff[t] = incl - c;   // exclusive
}

__global__ void scan_c_kernel() {
    int b = blockIdx.x, t = threadIdx.x;
    int idx = b * 256 + t;
    int c = (idx < NNODES) ? g_cnt[idx] : 0;
    int lane = t & 31, wid = t >> 5;
    int v = c;
    #pragma unroll
    for (int o = 1; o < 32; o <<= 1) {
        int n = __shfl_up_sync(0xffffffffu, v, o);
        if (lane >= o) v += n;
    }
    __shared__ int ws[8];
    if (lane == 31) ws[wid] = v;
    __syncthreads();
    if (wid == 0 && lane < 8) {
        int u = ws[lane];
        #pragma unroll
        for (int o = 1; o < 8; o <<= 1) {
            int n = __shfl_up_sync(0x000000ffu, u, o);
            if (lane >= o) u += n;
        }
        ws[lane] = u;
    }
    __syncthreads();
    int excl = (v - c) + (wid > 0 ? ws[wid - 1] : 0) + g_boff[b];
    if (idx < NNODES) g_start[idx] = excl;
    if (b == 0 && t == 0) g_start[NNODES] = NTOT;
}

// ---------------------------------------------------------------------------
// Kernel: place edges into CSR slots — atomic-free (uses precomputed rank)
// ---------------------------------------------------------------------------
__global__ void place_kernel(const int* __restrict__ lpr, const int* __restrict__ lpc,
                             const float* __restrict__ lpv,
                             const int* __restrict__ hpr, const int* __restrict__ hpc,
                             const float* __restrict__ hpv) {
    int i = blockIdx.x * blockDim.x + threadIdx.x;
    if (i >= NTOT) return;
    int row, col, flag;
    float val;
    if (i < NEDGES) {
        row = lpr[i]; col = lpc[i]; val = lpv[i]; flag = 1;
    } else {
        int e = i - NEDGES;
        row = hpr[e]; col = hpc[e]; val = hpv[e]; flag = 0;
    }
    int pos = g_start[row] + g_rank[i];
    g_edge[pos] = make_int2(col | (flag << 30), __float_as_int(val));
}

// ---------------------------------------------------------------------------
// Kernel: y = x @ W^T, stored as fp16. 128x128x8 SGEMM, 8x8 microtile, FFMA2.
// (bias/relu deferred to aggregate epilogue — they commute past the sparse op)
// ---------------------------------------------------------------------------
#define GBM 128
#define GBK 8
#define LDS_PAD 132   // 128 + 4, keeps float4 alignment

__global__ void __launch_bounds__(256)
gemm_y_kernel(const float* __restrict__ x,
              const float* __restrict__ W) {
    __shared__ float As[GBK][LDS_PAD];  // As[k][m] = x[m0+m][k0+k]
    __shared__ float Bs[GBK][LDS_PAD];  // Bs[k][n] = W[n][k]

    const int tid = threadIdx.x;
    const int tx  = tid & 15;
    const int ty  = tid >> 4;
    const int m0  = blockIdx.x * GBM;

    const int lrow = tid >> 1;
    const int lkq  = (tid & 1) * 4;

    unsigned long long acc[8][4];
    #pragma unroll
    for (int i = 0; i < 8; i++)
        #pragma unroll
        for (int j = 0; j < 4; j++) acc[i][j] = 0ull;

    for (int k0 = 0; k0 < DIN; k0 += GBK) {
        {
            int gm = m0 + lrow;
            float4 v = make_float4(0.f, 0.f, 0.f, 0.f);
            if (gm < NNODES)
                v = reinterpret_cast<const float4*>(x + (size_t)gm * DIN + k0 + lkq)[0];
            As[lkq + 0][lrow] = v.x; As[lkq + 1][lrow] = v.y;
            As[lkq + 2][lrow] = v.z; As[lkq + 3][lrow] = v.w;
        }
        {
            float4 v = reinterpret_cast<const float4*>(
                W + (size_t)lrow * DIN + k0 + lkq)[0];
            Bs[lkq + 0][lrow] = v.x; Bs[lkq + 1][lrow] = v.y;
            Bs[lkq + 2][lrow] = v.z; Bs[lkq + 3][lrow] = v.w;
        }
        __syncthreads();

        #pragma unroll
        for (int kk = 0; kk < GBK; kk++) {
            float a[8];
            {
                float4 a0 = reinterpret_cast<const float4*>(&As[kk][ty * 8])[0];
                float4 a1 = reinterpret_cast<const float4*>(&As[kk][ty * 8])[1];
                a[0]=a0.x; a[1]=a0.y; a[2]=a0.z; a[3]=a0.w;
                a[4]=a1.x; a[5]=a1.y; a[6]=a1.z; a[7]=a1.w;
            }
            unsigned long long bp[4];
            {
                const ulonglong2* bq = reinterpret_cast<const ulonglong2*>(&Bs[kk][tx * 8]);
                ulonglong2 q0 = bq[0], q1 = bq[1];
                bp[0] = q0.x; bp[1] = q0.y; bp[2] = q1.x; bp[3] = q1.y;
            }
            #pragma unroll
            for (int i = 0; i < 8; i++) {
                unsigned long long ap;
                asm("mov.b64 %0, {%1, %1};" : "=l"(ap) : "f"(a[i]));
                asm("fma.rn.f32x2 %0, %1, %2, %0;" : "+l"(acc[i][0]) : "l"(ap), "l"(bp[0]));
                asm("fma.rn.f32x2 %0, %1, %2, %0;" : "+l"(acc[i][1]) : "l"(ap), "l"(bp[1]));
                asm("fma.rn.f32x2 %0, %1, %2, %0;" : "+l"(acc[i][2]) : "l"(ap), "l"(bp[2]));
                asm("fma.rn.f32x2 %0, %1, %2, %0;" : "+l"(acc[i][3]) : "l"(ap), "l"(bp[3]));
            }
        }
        __syncthreads();
    }

    #pragma unroll
    for (int i = 0; i < 8; i++) {
        int gm = m0 + ty * 8 + i;
        if (gm >= NNODES) continue;
        float c[8];
        #pragma unroll
        for (int jp = 0; jp < 4; jp++)
            asm("mov.b64 {%0, %1}, %2;" : "=f"(c[jp*2]), "=f"(c[jp*2+1]) : "l"(acc[i][jp]));
        __half2 h0 = __floats2half2_rn(c[0], c[1]);
        __half2 h1 = __floats2half2_rn(c[2], c[3]);
        __half2 h2 = __floats2half2_rn(c[4], c[5]);
        __half2 h3 = __floats2half2_rn(c[6], c[7]);
        uint4 p;
        p.x = *reinterpret_cast<unsigned int*>(&h0);
        p.y = *reinterpret_cast<unsigned int*>(&h1);
        p.z = *reinterpret_cast<unsigned int*>(&h2);
        p.w = *reinterpret_cast<unsigned int*>(&h3);
        reinterpret_cast<uint4*>(g_yh + (size_t)gm * DOUT + tx * 8)[0] = p;
    }
}

// ---------------------------------------------------------------------------
// Kernel: software-pipelined gather-aggregate + bias + relu -> out.
// One warp per destination row; lane owns 4 output features (fp16 gather of
// y rows, fp32 accumulate). Pipeline: gathers for quad k+1 and edge loads for
// quad k+2 issue before the FMAs of quad k.
// ---------------------------------------------------------------------------
__device__ __forceinline__ float edge_w(int c, float v, float a, float ia) {
    return (c & 0x40000000) ? a * v : ia * v;
}

__device__ __forceinline__ void acc_half4(float4& acc, float w, uint2 h) {
    __half2 h0 = *reinterpret_cast<__half2*>(&h.x);
    __half2 h1 = *reinterpret_cast<__half2*>(&h.y);
    float2 f0 = __half22float2(h0);
    float2 f1 = __half22float2(h1);
    acc.x = fmaf(w, f0.x, acc.x); acc.y = fmaf(w, f0.y, acc.y);
    acc.z = fmaf(w, f1.x, acc.z); acc.w = fmaf(w, f1.y, acc.w);
}

__global__ void aggregate_out_kernel(const float* __restrict__ bias,
                                     float* __restrict__ out) {
    int warp = (blockIdx.x * blockDim.x + threadIdx.x) >> 5;
    int lane = threadIdx.x & 31;
    if (warp >= NNODES) return;

    int s = g_start[warp];
    int e = g_start[warp + 1];
    float a  = g_alpha[warp];
    float ia = 1.0f - a;

    float4 acc = make_float4(0.f, 0.f, 0.f, 0.f);
    int nq = (e - s) >> 2;     // full quads

    int2 E0[4], E1[4];
    uint2 G0[4];
    if (nq >= 1) {
        #pragma unroll
        for (int j = 0; j < 4; j++) E0[j] = g_edge[s + j];
        #pragma unroll
        for (int j = 0; j < 4; j++)
            G0[j] = reinterpret_cast<const uint2*>(
                g_yh + (size_t)(E0[j].x & 0x3FFFFFFF) * DOUT)[lane];
    }
    if (nq >= 2) {
        #pragma unroll
        for (int j = 0; j < 4; j++) E1[j] = g_edge[s + 4 + j];
    }

    for (int q = 0; q < nq; q++) {
        uint2 G1[4];
        if (q + 1 < nq) {
            #pragma unroll
            for (int j = 0; j < 4; j++)
                G1[j] = reinterpret_cast<const uint2*>(
                    g_yh + (size_t)(E1[j].x & 0x3FFFFFFF) * DOUT)[lane];
        }
        int2 E2[4];
        if (q + 2 < nq) {
            int base = s + (q + 2) * 4;
            #pragma unroll
            for (int j = 0; j < 4; j++) E2[j] = g_edge[base + j];
        }
        #pragma unroll
        for (int j = 0; j < 4; j++) {
            float w = edge_w(E0[j].x, __int_as_float(E0[j].y), a, ia);
            acc_half4(acc, w, G0[j]);
        }
        #pragma unroll
        for (int j = 0; j < 4; j++) { E0[j] = E1[j]; E1[j] = E2[j]; G0[j] = G1[j]; }
    }
    for (int i = s + nq * 4; i < e; i++) {
        int2 e0 = g_edge[i];
        float w = edge_w(e0.x, __int_as_float(e0.y), a, ia);
        uint2 g = reinterpret_cast<const uint2*>(
            g_yh + (size_t)(e0.x & 0x3FFFFFFF) * DOUT)[lane];
        acc_half4(acc, w, g);
    }

    float4 bv = reinterpret_cast<const float4*>(bias)[lane];
    float4 v;
    v.x = fmaxf(acc.x + bv.x, 0.f);
    v.y = fmaxf(acc.y + bv.y, 0.f);
    v.z = fmaxf(acc.z + bv.z, 0.f);
    v.w = fmaxf(acc.w + bv.w, 0.f);
    reinterpret_cast<float4*>(out + (size_t)warp * DOUT)[lane] = v;
}

// ---------------------------------------------------------------------------
// Launch
// Inputs: x, lp_rows, lp_cols, lp_vals, hp_rows, hp_cols, hp_vals,
//         alpha_w, alpha_b, W, b
// Output: [out (N*DOUT floats)] then [alpha (N floats)]
// ---------------------------------------------------------------------------
extern "C" void kernel_launch(void* const* d_in, const int* in_sizes, int n_in,
                              void* d_out, int out_size) {
    const float* x   = (const float*)d_in[0];
    const int*   lpr = (const int*)  d_in[1];
    const int*   lpc = (const int*)  d_in[2];
    const float* lpv = (const float*)d_in[3];
    const int*   hpr = (const int*)  d_in[4];
    const int*   hpc = (const int*)  d_in[5];
    const float* hpv = (const float*)d_in[6];
    const float* aw  = (const float*)d_in[7];
    const float* ab  = (const float*)d_in[8];
    const float* W   = (const float*)d_in[9];
    const float* b   = (const float*)d_in[10];

    float* out       = (float*)d_out;
    float* alpha_out = (float*)d_out + (out_size - NNODES);

    // 1) zero histogram
    zero_cnt_kernel<<<(NNODES + 255) / 256, 256>>>();

    // 2) alpha gate (one warp per node)
    alpha_kernel<<<(NNODES + 7) / 8, 256>>>(x, aw, ab, alpha_out);

    // 3) y = x @ W^T (fp16 output)
    gemm_y_kernel<<<(NNODES + GBM - 1) / GBM, 256>>>(x, W);

    // 4) histogram + rank (single atomic pass)
    hist_rank_kernel<<<(NTOT + 255) / 256, 256>>>(lpr, hpr);

    // 5) 3-phase exclusive scan -> CSR row starts
    scan_a_kernel<<<NB_SCAN, 256>>>();
    scan_b_kernel<<<1, 256>>>();
    scan_c_kernel<<<NB_SCAN, 256>>>();

    // 6) place edges into CSR slots (atomic-free)
    place_kernel<<<(NTOT + 255) / 256, 256>>>(lpr, lpc, lpv, hpr, hpc, hpv);

    // 7) pipelined gather-aggregate + bias + relu -> out
    aggregate_out_kernel<<<(NNODES + 7) / 8, 256>>>(b, out);
}